// round 3
// baseline (speedup 1.0000x reference)
#include <cuda_runtime.h>

#define NA 200000
#define NDG 50000
#define NB 8192
#define EPSBN 1e-5f

// ---------------- scratch (static device globals; no runtime alloc) ----------------
__device__ float g_G[(size_t)NA * 272];   // gather/concat buffer (max K = 272)
__device__ float g_H[(size_t)NA * 128];   // layer-1 pre-BN x, then normalized h1 (in place)
__device__ float g_X[(size_t)NA * 128];   // layer-2 pre-BN x, then normalized h2 (in place)
__device__ float g_stats[512];            // [0:128) sum1, [128:256) sumsq1, [256:384) sum2, [384:512) sumsq2

__global__ void zero_stats_kernel() {
    int i = threadIdx.x;
    if (i < 512) g_stats[i] = 0.f;
}

// ---------------- gather: G[row] = [ self (KIN) | sum atom-nbrs (KIN) | sum bond-nbrs (16) ] ----
template <int KIN>
__global__ void gather_kernel(const float* __restrict__ Hin,
                              const float* __restrict__ bond,
                              const int* __restrict__ a1, const int* __restrict__ a2,
                              const int* __restrict__ a3, const int* __restrict__ a4,
                              const int* __restrict__ b1, const int* __restrict__ b2,
                              const int* __restrict__ b3, const int* __restrict__ b4) {
    constexpr int CK  = 2 * KIN + 16;
    constexpr int CK4 = CK / 4;
    long long idx = (long long)blockIdx.x * blockDim.x + threadIdx.x;
    if (idx >= (long long)NA * CK4) return;
    int row = (int)(idx / CK4);
    int c4  = (int)(idx - (long long)row * CK4);
    int d   = row / NDG;           // 0..3  (degree = d+1)
    int r   = row - d * NDG;
    int deg = d + 1;
    const int* aidx; const int* bidx;
    if (d == 0)      { aidx = a1; bidx = b1; }
    else if (d == 1) { aidx = a2; bidx = b2; }
    else if (d == 2) { aidx = a3; bidx = b3; }
    else             { aidx = a4; bidx = b4; }
    int c = c4 * 4;
    float4 out;
    if (c < KIN) {
        out = *(const float4*)(Hin + (size_t)row * KIN + c);
    } else if (c < 2 * KIN) {
        int cc = c - KIN;
        float4 s = make_float4(0.f, 0.f, 0.f, 0.f);
        #pragma unroll 4
        for (int t = 0; t < deg; t++) {
            int nb = aidx[r * deg + t];
            float4 v = *(const float4*)(Hin + (size_t)nb * KIN + cc);
            s.x += v.x; s.y += v.y; s.z += v.z; s.w += v.w;
        }
        out = s;
    } else {
        int cc = c - 2 * KIN;
        float4 s = make_float4(0.f, 0.f, 0.f, 0.f);
        #pragma unroll 4
        for (int t = 0; t < deg; t++) {
            int nb = bidx[r * deg + t];
            float4 v = *(const float4*)(bond + (size_t)nb * 16 + cc);
            s.x += v.x; s.y += v.y; s.z += v.z; s.w += v.w;
        }
        out = s;
    }
    *(float4*)(g_G + (size_t)row * CK + c) = out;
}

// ---------------- conv GEMM: X[row] = G[row] @ [selfW; dW_d] + bias ; accumulate BN stats ----
template <int KIN>
__global__ void conv_kernel(const float* __restrict__ selfW,
                            const float* __restrict__ dW1, const float* __restrict__ dW2,
                            const float* __restrict__ dW3, const float* __restrict__ dW4,
                            const float* __restrict__ bias,
                            float* __restrict__ Xout,
                            int statsOff, int blocksPerDeg) {
    constexpr int CK  = 2 * KIN + 16;
    constexpr int CK4 = CK / 4;
    constexpr int WS  = CK + 4;          // padded transposed-W row stride (floats)
    extern __shared__ float sm[];
    float* Wt     = sm;                  // 128 * WS
    float* rowbuf = Wt + 128 * WS;       // 8 * CK
    float* bias_s = rowbuf + 8 * CK;     // 128

    int j     = threadIdx.x;             // output column
    int d     = blockIdx.x / blocksPerDeg;
    int chunk = blockIdx.x - d * blocksPerDeg;
    int rowbase = d * NDG + chunk * 128;
    int rowend  = min(d * NDG + NDG, rowbase + 128);
    const float* dW = (d == 0) ? dW1 : (d == 1) ? dW2 : (d == 2) ? dW3 : dW4;

    // stage transposed stacked weights: Wt[j][k] = Wstk[k][j]
    for (int k = 0; k < CK; k++) {
        float w = (k < KIN) ? selfW[k * 128 + j] : dW[(k - KIN) * 128 + j];
        Wt[j * WS + k] = w;
    }
    bias_s[j] = bias[j];
    __syncthreads();

    float psum = 0.f, psq = 0.f;
    for (int rb = rowbase; rb < rowend; rb += 8) {
        int nr = min(8, rowend - rb);
        for (int t = j; t < nr * CK4; t += 128) {
            int s = t / CK4; int cc4 = t - s * CK4;
            ((float4*)rowbuf)[s * CK4 + cc4] =
                ((const float4*)(g_G + (size_t)(rb + s) * CK))[cc4];
        }
        __syncthreads();

        float acc[8];
        #pragma unroll
        for (int s = 0; s < 8; s++) acc[s] = bias_s[j];
        const float4* WtR = (const float4*)(Wt + j * WS);
        const float4* RB  = (const float4*)rowbuf;
        #pragma unroll 4
        for (int k4 = 0; k4 < CK4; k4++) {
            float4 w = WtR[k4];
            #pragma unroll
            for (int s = 0; s < 8; s++) {
                float4 h = RB[s * CK4 + k4];
                acc[s] += w.x * h.x + w.y * h.y + w.z * h.z + w.w * h.w;
            }
        }
        #pragma unroll
        for (int s = 0; s < 8; s++) {
            if (s < nr) {
                float x = acc[s];
                Xout[(size_t)(rb + s) * 128 + j] = x;
                psum += x; psq += x * x;
            }
        }
        __syncthreads();
    }
    atomicAdd(&g_stats[statsOff + j], psum);
    atomicAdd(&g_stats[statsOff + 128 + j], psq);
}

// ---------------- BN (affine=False, biased stats) + relu, in place ----------------
__global__ void norm_kernel(float* __restrict__ X, int statsOff) {
    __shared__ float sc[128];
    __shared__ float sh[128];
    if (threadIdx.x < 128) {
        float mean = g_stats[statsOff + threadIdx.x] * (1.f / NA);
        float var  = g_stats[statsOff + 128 + threadIdx.x] * (1.f / NA) - mean * mean;
        float r = rsqrtf(var + EPSBN);
        sc[threadIdx.x] = r;
        sh[threadIdx.x] = -mean * r;
    }
    __syncthreads();
    size_t total  = (size_t)NA * 128;
    size_t stride = (size_t)gridDim.x * blockDim.x;
    for (size_t i = (size_t)blockIdx.x * blockDim.x + threadIdx.x; i < total; i += stride) {
        int jj = (int)(i & 127);
        X[i] = fmaxf(0.f, fmaf(X[i], sc[jj], sh[jj]));
    }
}

// ---------------- fp update: fp[mol] += segsum(softmax(H @ W + b)) ----------------
template <int KIN>
__global__ void fp_kernel(const float* __restrict__ Hin,
                          const float* __restrict__ W, const float* __restrict__ bias,
                          const int* __restrict__ mol_ids,
                          float* __restrict__ fp) {
    constexpr int K4 = KIN / 4;
    constexpr int WS = KIN + 4;
    extern __shared__ float sm[];
    float* Wt     = sm;                      // 128 * WS
    float* rowbuf = Wt + 128 * WS;           // 8 * KIN
    float* bias_s = rowbuf + 8 * KIN;        // 128
    float* red    = bias_s + 128;            // 32 (= 8 rows x 4 warps)
    int*   mols   = (int*)(red + 32);        // 128

    int j = threadIdx.x;
    int warp = j >> 5, lane = j & 31;
    int rowbase = blockIdx.x * 128;
    int rowend  = min(NA, rowbase + 128);

    for (int k = 0; k < KIN; k++) Wt[j * WS + k] = W[k * 128 + j];
    bias_s[j] = bias[j];
    if (rowbase + j < NA) mols[j] = mol_ids[rowbase + j];
    __syncthreads();

    int cur_mol = -1; float run = 0.f;
    for (int rb = rowbase; rb < rowend; rb += 8) {
        int nr = min(8, rowend - rb);
        for (int t = j; t < nr * K4; t += 128) {
            int s = t / K4; int c4 = t - s * K4;
            ((float4*)rowbuf)[s * K4 + c4] =
                ((const float4*)(Hin + (size_t)(rb + s) * KIN))[c4];
        }
        __syncthreads();

        float acc[8];
        #pragma unroll
        for (int s = 0; s < 8; s++) acc[s] = bias_s[j];
        const float4* WtR = (const float4*)(Wt + j * WS);
        const float4* RB  = (const float4*)rowbuf;
        #pragma unroll 4
        for (int k4 = 0; k4 < K4; k4++) {
            float4 w = WtR[k4];
            #pragma unroll
            for (int s = 0; s < 8; s++) {
                float4 h = RB[s * K4 + k4];
                acc[s] += w.x * h.x + w.y * h.y + w.z * h.z + w.w * h.w;
            }
        }

        // row max over 128 threads
        #pragma unroll
        for (int s = 0; s < 8; s++) {
            float v = acc[s];
            v = fmaxf(v, __shfl_xor_sync(0xffffffffu, v, 16));
            v = fmaxf(v, __shfl_xor_sync(0xffffffffu, v, 8));
            v = fmaxf(v, __shfl_xor_sync(0xffffffffu, v, 4));
            v = fmaxf(v, __shfl_xor_sync(0xffffffffu, v, 2));
            v = fmaxf(v, __shfl_xor_sync(0xffffffffu, v, 1));
            if (lane == 0) red[s * 4 + warp] = v;
        }
        __syncthreads();
        float m[8];
        #pragma unroll
        for (int s = 0; s < 8; s++)
            m[s] = fmaxf(fmaxf(red[s * 4 + 0], red[s * 4 + 1]),
                         fmaxf(red[s * 4 + 2], red[s * 4 + 3]));
        __syncthreads();

        // exp + row sum
        float e[8];
        #pragma unroll
        for (int s = 0; s < 8; s++) {
            float v = __expf(acc[s] - m[s]);
            e[s] = v;
            v += __shfl_xor_sync(0xffffffffu, v, 16);
            v += __shfl_xor_sync(0xffffffffu, v, 8);
            v += __shfl_xor_sync(0xffffffffu, v, 4);
            v += __shfl_xor_sync(0xffffffffu, v, 2);
            v += __shfl_xor_sync(0xffffffffu, v, 1);
            if (lane == 0) red[s * 4 + warp] = v;
        }
        __syncthreads();
        #pragma unroll
        for (int s = 0; s < 8; s++) {
            float tot = red[s * 4 + 0] + red[s * 4 + 1] + red[s * 4 + 2] + red[s * 4 + 3];
            e[s] = e[s] / tot;
        }
        __syncthreads();

        // sorted-run segment accumulation (branch is uniform across the block)
        for (int s = 0; s < nr; s++) {
            int mm = mols[rb - rowbase + s];
            if (mm != cur_mol) {
                if (cur_mol >= 0) atomicAdd(&fp[(size_t)cur_mol * 128 + j], run);
                cur_mol = mm; run = e[s];
            } else {
                run += e[s];
            }
        }
    }
    if (cur_mol >= 0) atomicAdd(&fp[(size_t)cur_mol * 128 + j], run);
}

// ---------------- launch ----------------
extern "C" void kernel_launch(void* const* d_in, const int* in_sizes, int n_in,
                              void* d_out, int out_size) {
    const float *atom, *bond, *W0, *b0, *W1, *b1, *W2, *b2;
    const float *c1sW, *c1b, *c1d1, *c1d2, *c1d3, *c1d4;
    const float *c2sW, *c2b, *c2d1, *c2d2, *c2d3, *c2d4;
    const int *a1, *a2, *a3, *a4, *e1, *e2, *e3, *e4, *mol;

    if (in_sizes[0] == 12800000) {
        // atom_repr first
        atom = (const float*)d_in[0];
        bond = (const float*)d_in[1];
        if (in_sizes[2] == 8192) {
            // reference() signature order:
            // atom, bond, W0,b0,W1,b1,W2,b2, c1sW,c1b,c1d1..4, c2sW,c2b,c2d1..4,
            // a1..a4, b1..b4, mol
            W0 = (const float*)d_in[2];  b0 = (const float*)d_in[3];
            W1 = (const float*)d_in[4];  b1 = (const float*)d_in[5];
            W2 = (const float*)d_in[6];  b2 = (const float*)d_in[7];
            c1sW = (const float*)d_in[8];  c1b = (const float*)d_in[9];
            c1d1 = (const float*)d_in[10]; c1d2 = (const float*)d_in[11];
            c1d3 = (const float*)d_in[12]; c1d4 = (const float*)d_in[13];
            c2sW = (const float*)d_in[14]; c2b = (const float*)d_in[15];
            c2d1 = (const float*)d_in[16]; c2d2 = (const float*)d_in[17];
            c2d3 = (const float*)d_in[18]; c2d4 = (const float*)d_in[19];
            a1 = (const int*)d_in[20]; a2 = (const int*)d_in[21];
            a3 = (const int*)d_in[22]; a4 = (const int*)d_in[23];
            e1 = (const int*)d_in[24]; e2 = (const int*)d_in[25];
            e3 = (const int*)d_in[26]; e4 = (const int*)d_in[27];
            mol = (const int*)d_in[28];
        } else if (in_sizes[3] == 50000) {
            // setup_inputs() dict order — nbr arrays INTERLEAVED per degree:
            // atom, bond, a1, b1, a2, b2, a3, b3, a4, b4, mol, W0,b0,W1,b1,W2,b2,
            // c1sW, c1b, c1d1..4, c2sW, c2b, c2d1..4
            a1 = (const int*)d_in[2];  e1 = (const int*)d_in[3];
            a2 = (const int*)d_in[4];  e2 = (const int*)d_in[5];
            a3 = (const int*)d_in[6];  e3 = (const int*)d_in[7];
            a4 = (const int*)d_in[8];  e4 = (const int*)d_in[9];
            mol = (const int*)d_in[10];
            W0 = (const float*)d_in[11]; b0 = (const float*)d_in[12];
            W1 = (const float*)d_in[13]; b1 = (const float*)d_in[14];
            W2 = (const float*)d_in[15]; b2 = (const float*)d_in[16];
            c1sW = (const float*)d_in[17]; c1b = (const float*)d_in[18];
            c1d1 = (const float*)d_in[19]; c1d2 = (const float*)d_in[20];
            c1d3 = (const float*)d_in[21]; c1d4 = (const float*)d_in[22];
            c2sW = (const float*)d_in[23]; c2b = (const float*)d_in[24];
            c2d1 = (const float*)d_in[25]; c2d2 = (const float*)d_in[26];
            c2d3 = (const float*)d_in[27]; c2d4 = (const float*)d_in[28];
        } else {
            // grouped order: atom, bond, a1..a4, b1..b4, mol, W..., c...
            a1 = (const int*)d_in[2];  a2 = (const int*)d_in[3];
            a3 = (const int*)d_in[4];  a4 = (const int*)d_in[5];
            e1 = (const int*)d_in[6];  e2 = (const int*)d_in[7];
            e3 = (const int*)d_in[8];  e4 = (const int*)d_in[9];
            mol = (const int*)d_in[10];
            W0 = (const float*)d_in[11]; b0 = (const float*)d_in[12];
            W1 = (const float*)d_in[13]; b1 = (const float*)d_in[14];
            W2 = (const float*)d_in[15]; b2 = (const float*)d_in[16];
            c1sW = (const float*)d_in[17]; c1b = (const float*)d_in[18];
            c1d1 = (const float*)d_in[19]; c1d2 = (const float*)d_in[20];
            c1d3 = (const float*)d_in[21]; c1d4 = (const float*)d_in[22];
            c2sW = (const float*)d_in[23]; c2b = (const float*)d_in[24];
            c2d1 = (const float*)d_in[25]; c2d2 = (const float*)d_in[26];
            c2d3 = (const float*)d_in[27]; c2d4 = (const float*)d_in[28];
        }
    } else {
        // alphabetical key order:
        // a_nbr1..4, atom_repr, b_nbr1..4, bond_repr, c1_bias, c1_dW1..4, c1_selfW,
        // c2_bias, c2_dW1..4, c2_selfW, mol_ids, out_*
        a1 = (const int*)d_in[0];  a2 = (const int*)d_in[1];
        a3 = (const int*)d_in[2];  a4 = (const int*)d_in[3];
        atom = (const float*)d_in[4];
        e1 = (const int*)d_in[5];  e2 = (const int*)d_in[6];
        e3 = (const int*)d_in[7];  e4 = (const int*)d_in[8];
        bond = (const float*)d_in[9];
        c1b = (const float*)d_in[10];
        c1d1 = (const float*)d_in[11]; c1d2 = (const float*)d_in[12];
        c1d3 = (const float*)d_in[13]; c1d4 = (const float*)d_in[14];
        c1sW = (const float*)d_in[15];
        c2b = (const float*)d_in[16];
        c2d1 = (const float*)d_in[17]; c2d2 = (const float*)d_in[18];
        c2d3 = (const float*)d_in[19]; c2d4 = (const float*)d_in[20];
        c2sW = (const float*)d_in[21];
        mol = (const int*)d_in[22];
        if (in_sizes[24] == 128) {
            // paired: W0, b0, W1, b1, W2, b2
            W0 = (const float*)d_in[23]; b0 = (const float*)d_in[24];
            W1 = (const float*)d_in[25]; b1 = (const float*)d_in[26];
            W2 = (const float*)d_in[27]; b2 = (const float*)d_in[28];
        } else {
            // strict ASCII sort: out_W0, out_W1, out_W2, out_b0, out_b1, out_b2
            W0 = (const float*)d_in[23]; W1 = (const float*)d_in[24];
            W2 = (const float*)d_in[25];
            b0 = (const float*)d_in[26]; b1 = (const float*)d_in[27];
            b2 = (const float*)d_in[28];
        }
    }

    float* fp = (float*)d_out;

    float *Hp, *Xp;
    cudaGetSymbolAddress((void**)&Hp, g_H);
    cudaGetSymbolAddress((void**)&Xp, g_X);

    // smem sizes (bytes)
    const int CONV64_SMEM  = (128 * (144 + 4) + 8 * 144 + 128) * 4;              // 80896
    const int CONV128_SMEM = (128 * (272 + 4) + 8 * 272 + 128) * 4;              // 150528
    const int FP64_SMEM    = (128 * (64 + 4) + 8 * 64 + 128 + 32) * 4 + 128 * 4; // 38016
    const int FP128_SMEM   = (128 * (128 + 4) + 8 * 128 + 128 + 32) * 4 + 128 * 4; // 72832

    cudaFuncSetAttribute(conv_kernel<64>,  cudaFuncAttributeMaxDynamicSharedMemorySize, CONV64_SMEM);
    cudaFuncSetAttribute(conv_kernel<128>, cudaFuncAttributeMaxDynamicSharedMemorySize, CONV128_SMEM);
    cudaFuncSetAttribute(fp_kernel<64>,    cudaFuncAttributeMaxDynamicSharedMemorySize, FP64_SMEM);
    cudaFuncSetAttribute(fp_kernel<128>,   cudaFuncAttributeMaxDynamicSharedMemorySize, FP128_SMEM);

    const int blocksPerDeg = (NDG + 127) / 128;   // 391
    const int fpBlocks     = (NA + 127) / 128;    // 1563

    cudaMemsetAsync(d_out, 0, (size_t)out_size * sizeof(float));
    zero_stats_kernel<<<1, 512>>>();

    // fp += segsum(softmax(atom @ W0 + b0))
    fp_kernel<64><<<fpBlocks, 128, FP64_SMEM>>>(atom, W0, b0, mol, fp);

    // layer 1 conv
    {
        long long total = (long long)NA * 36;   // CK4 for KIN=64
        int gblocks = (int)((total + 255) / 256);
        gather_kernel<64><<<gblocks, 256>>>(atom, bond, a1, a2, a3, a4, e1, e2, e3, e4);
    }
    conv_kernel<64><<<4 * blocksPerDeg, 128, CONV64_SMEM>>>(
        c1sW, c1d1, c1d2, c1d3, c1d4, c1b, Hp, 0, blocksPerDeg);
    norm_kernel<<<2048, 256>>>(Hp, 0);

    // fp += segsum(softmax(h1 @ W1 + b1))
    fp_kernel<128><<<fpBlocks, 128, FP128_SMEM>>>(Hp, W1, b1, mol, fp);

    // layer 2 conv
    {
        long long total = (long long)NA * 68;   // CK4 for KIN=128
        int gblocks = (int)((total + 255) / 256);
        gather_kernel<128><<<gblocks, 256>>>(Hp, bond, a1, a2, a3, a4, e1, e2, e3, e4);
    }
    conv_kernel<128><<<4 * blocksPerDeg, 128, CONV128_SMEM>>>(
        c2sW, c2d1, c2d2, c2d3, c2d4, c2b, Xp, 256, blocksPerDeg);
    norm_kernel<<<2048, 256>>>(Xp, 256);

    // fp += segsum(softmax(h2 @ W2 + b2))
    fp_kernel<128><<<fpBlocks, 128, FP128_SMEM>>>(Xp, W2, b2, mol, fp);
}

// round 4
// speedup vs baseline: 2.2394x; 2.2394x over previous
#include <cuda_runtime.h>

#define NA 200000
#define NDG 50000
#define NB 8192
#define EPSBN 1e-5f
#define TPD 391           // row tiles per degree = ceil(50000/128)
#define FPB 1563          // fp blocks = ceil(200000/128)

typedef unsigned long long u64;

__device__ __forceinline__ u64 pack2(float lo, float hi) {
    u64 r; asm("mov.b64 %0, {%1, %2};" : "=l"(r) : "f"(lo), "f"(hi)); return r;
}
__device__ __forceinline__ void unpack2(u64 v, float& lo, float& hi) {
    asm("mov.b64 {%0, %1}, %2;" : "=f"(lo), "=f"(hi) : "l"(v));
}
__device__ __forceinline__ u64 ffma2(u64 a, u64 b, u64 c) {
    u64 d; asm("fma.rn.f32x2 %0, %1, %2, %3;" : "=l"(d) : "l"(a), "l"(b), "l"(c)); return d;
}

// ---------------- scratch ----------------
__device__ float g_G[(size_t)NA * 272];
__device__ float g_H[(size_t)NA * 128];
__device__ float g_X[(size_t)NA * 128];
__device__ float g_stats[512];

__global__ void zero_stats_kernel() {
    int i = threadIdx.x;
    if (i < 512) g_stats[i] = 0.f;
}

// ---------------- gather (unchanged) ----------------
template <int KIN>
__global__ void gather_kernel(const float* __restrict__ Hin,
                              const float* __restrict__ bond,
                              const int* __restrict__ a1, const int* __restrict__ a2,
                              const int* __restrict__ a3, const int* __restrict__ a4,
                              const int* __restrict__ b1, const int* __restrict__ b2,
                              const int* __restrict__ b3, const int* __restrict__ b4) {
    constexpr int CK  = 2 * KIN + 16;
    constexpr int CK4 = CK / 4;
    long long idx = (long long)blockIdx.x * blockDim.x + threadIdx.x;
    if (idx >= (long long)NA * CK4) return;
    int row = (int)(idx / CK4);
    int c4  = (int)(idx - (long long)row * CK4);
    int d   = row / NDG;
    int r   = row - d * NDG;
    int deg = d + 1;
    const int* aidx; const int* bidx;
    if (d == 0)      { aidx = a1; bidx = b1; }
    else if (d == 1) { aidx = a2; bidx = b2; }
    else if (d == 2) { aidx = a3; bidx = b3; }
    else             { aidx = a4; bidx = b4; }
    int c = c4 * 4;
    float4 out;
    if (c < KIN) {
        out = *(const float4*)(Hin + (size_t)row * KIN + c);
    } else if (c < 2 * KIN) {
        int cc = c - KIN;
        float4 s = make_float4(0.f, 0.f, 0.f, 0.f);
        #pragma unroll 4
        for (int t = 0; t < deg; t++) {
            int nb = aidx[r * deg + t];
            float4 v = *(const float4*)(Hin + (size_t)nb * KIN + cc);
            s.x += v.x; s.y += v.y; s.z += v.z; s.w += v.w;
        }
        out = s;
    } else {
        int cc = c - 2 * KIN;
        float4 s = make_float4(0.f, 0.f, 0.f, 0.f);
        #pragma unroll 4
        for (int t = 0; t < deg; t++) {
            int nb = bidx[r * deg + t];
            float4 v = *(const float4*)(bond + (size_t)nb * 16 + cc);
            s.x += v.x; s.y += v.y; s.z += v.z; s.w += v.w;
        }
        out = s;
    }
    *(float4*)(g_G + (size_t)row * CK + c) = out;
}

// ---------------- shared GEMM machinery ----------------
// smem chunk: As[buf][k][row] (transposed, 132 stride), Ws[buf][k][col]
#define ARS 132

__device__ __forceinline__ void sts_chunk(float* As, float* Ws, int tid,
                                          float4 a0, float4 a1, float4 w0, float4 w1) {
    int rl = tid & 127, kk = (tid >> 7) * 8;
    As[(kk + 0) * ARS + rl] = a0.x; As[(kk + 1) * ARS + rl] = a0.y;
    As[(kk + 2) * ARS + rl] = a0.z; As[(kk + 3) * ARS + rl] = a0.w;
    As[(kk + 4) * ARS + rl] = a1.x; As[(kk + 5) * ARS + rl] = a1.y;
    As[(kk + 6) * ARS + rl] = a1.z; As[(kk + 7) * ARS + rl] = a1.w;
    int f0 = tid, f1 = tid + 256;                 // float4 index: k = f>>5, j = (f&31)*4
    *(float4*)&Ws[(f0 >> 5) * 128 + (f0 & 31) * 4] = w0;
    *(float4*)&Ws[(f1 >> 5) * 128 + (f1 & 31) * 4] = w1;
}

__device__ __forceinline__ void compute_chunk(const float* As, const float* Ws,
                                              int tx, int ty, u64 acc[8][4]) {
    #pragma unroll 4
    for (int k = 0; k < 16; k++) {
        float4 a0 = *(const float4*)&As[k * ARS + ty * 8];
        float4 a1 = *(const float4*)&As[k * ARS + ty * 8 + 4];
        float4 w0 = *(const float4*)&Ws[k * 128 + tx * 8];
        float4 w1 = *(const float4*)&Ws[k * 128 + tx * 8 + 4];
        u64 wv0 = pack2(w0.x, w0.y), wv1 = pack2(w0.z, w0.w);
        u64 wv2 = pack2(w1.x, w1.y), wv3 = pack2(w1.z, w1.w);
        float av[8] = {a0.x, a0.y, a0.z, a0.w, a1.x, a1.y, a1.z, a1.w};
        #pragma unroll
        for (int i = 0; i < 8; i++) {
            u64 aa = pack2(av[i], av[i]);
            acc[i][0] = ffma2(aa, wv0, acc[i][0]);
            acc[i][1] = ffma2(aa, wv1, acc[i][1]);
            acc[i][2] = ffma2(aa, wv2, acc[i][2]);
            acc[i][3] = ffma2(aa, wv3, acc[i][3]);
        }
    }
}

// ---------------- conv GEMM v2: 128x128 block tile, 8x8 thread tile, f32x2 ----
template <int KIN>
__global__ __launch_bounds__(256, 2)
void conv_kernel(const float* __restrict__ selfW,
                 const float* __restrict__ dW1, const float* __restrict__ dW2,
                 const float* __restrict__ dW3, const float* __restrict__ dW4,
                 const float* __restrict__ bias,
                 float* __restrict__ Xout, int statsOff) {
    constexpr int CK  = 2 * KIN + 16;
    constexpr int NCH = CK / 16;
    __shared__ float As[2][16 * ARS];
    __shared__ float Ws[2][16 * 128];

    int tid = threadIdx.x;
    int tx = tid & 15, ty = tid >> 4;
    int d    = blockIdx.x / TPD;
    int tile = blockIdx.x - d * TPD;
    int rowbase = d * NDG + tile * 128;
    int rowend  = min((d + 1) * NDG, rowbase + 128);
    const float* dW = (d == 0) ? dW1 : (d == 1) ? dW2 : (d == 2) ? dW3 : dW4;

    int rl = tid & 127, kk = (tid >> 7) * 8;
    int rg = rowbase + rl;
    bool rvalid = rg < rowend;
    const float* Grow = g_G + (size_t)rg * CK + kk;

    // bias for this thread's 8 cols
    float bcol[8];
    *(float4*)&bcol[0] = *(const float4*)&bias[tx * 8];
    *(float4*)&bcol[4] = *(const float4*)&bias[tx * 8 + 4];

    // stage chunk 0
    {
        float4 a0 = make_float4(0,0,0,0), a1 = a0;
        if (rvalid) { a0 = *(const float4*)Grow; a1 = *(const float4*)(Grow + 4); }
        const float* wsrc = selfW;   // k0 = 0 < KIN always
        float4 w0 = ((const float4*)wsrc)[tid];
        float4 w1 = ((const float4*)wsrc)[tid + 256];
        sts_chunk(As[0], Ws[0], tid, a0, a1, w0, w1);
    }
    __syncthreads();

    u64 acc[8][4];
    #pragma unroll
    for (int i = 0; i < 8; i++)
        #pragma unroll
        for (int q = 0; q < 4; q++) acc[i][q] = 0ull;

    for (int c = 0; c < NCH; c++) {
        int buf = c & 1;
        float4 a0, a1, w0, w1;
        bool havenext = (c + 1 < NCH);
        if (havenext) {
            int k0 = (c + 1) * 16;
            a0 = make_float4(0,0,0,0); a1 = a0;
            if (rvalid) { a0 = *(const float4*)(Grow + k0); a1 = *(const float4*)(Grow + k0 + 4); }
            const float* wsrc = (k0 < KIN) ? (selfW + (size_t)k0 * 128)
                                           : (dW + (size_t)(k0 - KIN) * 128);
            w0 = ((const float4*)wsrc)[tid];
            w1 = ((const float4*)wsrc)[tid + 256];
        }
        compute_chunk(As[buf], Ws[buf], tx, ty, acc);
        if (havenext) sts_chunk(As[buf ^ 1], Ws[buf ^ 1], tid, a0, a1, w0, w1);
        __syncthreads();
    }

    // epilogue: bias, store, BN partials
    float psum[8], psq[8];
    #pragma unroll
    for (int j = 0; j < 8; j++) { psum[j] = 0.f; psq[j] = 0.f; }
    #pragma unroll
    for (int i = 0; i < 8; i++) {
        int r = rowbase + ty * 8 + i;
        float x[8];
        unpack2(acc[i][0], x[0], x[1]); unpack2(acc[i][1], x[2], x[3]);
        unpack2(acc[i][2], x[4], x[5]); unpack2(acc[i][3], x[6], x[7]);
        #pragma unroll
        for (int j = 0; j < 8; j++) x[j] += bcol[j];
        if (r < rowend) {
            float* outp = Xout + (size_t)r * 128 + tx * 8;
            *(float4*)outp       = make_float4(x[0], x[1], x[2], x[3]);
            *(float4*)(outp + 4) = make_float4(x[4], x[5], x[6], x[7]);
            #pragma unroll
            for (int j = 0; j < 8; j++) { psum[j] += x[j]; psq[j] += x[j] * x[j]; }
        }
    }
    // tree-reduce stats: redS[ty][col], redQ[ty][col] in As region (4224 floats >= 4096)
    float* redS = &As[0][0];
    float* redQ = redS + 2048;
    #pragma unroll
    for (int j = 0; j < 8; j++) {
        redS[ty * 128 + tx * 8 + j] = psum[j];
        redQ[ty * 128 + tx * 8 + j] = psq[j];
    }
    __syncthreads();
    if (tid < 128) {
        float s = 0.f, q = 0.f;
        #pragma unroll
        for (int t = 0; t < 16; t++) { s += redS[t * 128 + tid]; q += redQ[t * 128 + tid]; }
        atomicAdd(&g_stats[statsOff + tid], s);
        atomicAdd(&g_stats[statsOff + 128 + tid], q);
    }
}

// ---------------- BN + relu (unchanged) ----------------
__global__ void norm_kernel(float* __restrict__ X, int statsOff) {
    __shared__ float sc[128];
    __shared__ float sh[128];
    if (threadIdx.x < 128) {
        float mean = g_stats[statsOff + threadIdx.x] * (1.f / NA);
        float var  = g_stats[statsOff + 128 + threadIdx.x] * (1.f / NA) - mean * mean;
        float r = rsqrtf(var + EPSBN);
        sc[threadIdx.x] = r;
        sh[threadIdx.x] = -mean * r;
    }
    __syncthreads();
    size_t total  = (size_t)NA * 128;
    size_t stride = (size_t)gridDim.x * blockDim.x;
    for (size_t i = (size_t)blockIdx.x * blockDim.x + threadIdx.x; i < total; i += stride) {
        int jj = (int)(i & 127);
        X[i] = fmaxf(0.f, fmaf(X[i], sc[jj], sh[jj]));
    }
}

// ---------------- fp update v2: tiled GEMM + 16-lane-shuffle softmax + seg sum ----
template <int KIN>
__global__ __launch_bounds__(256, 2)
void fp_kernel(const float* __restrict__ Hin,
               const float* __restrict__ W, const float* __restrict__ bias,
               const int* __restrict__ mol_ids,
               float* __restrict__ fp) {
    constexpr int NCH = KIN / 16;
    __shared__ float As[2][16 * ARS];
    __shared__ float Ws[2][16 * 128];

    int tid = threadIdx.x;
    int tx = tid & 15, ty = tid >> 4;
    int rowbase = blockIdx.x * 128;

    int rl = tid & 127, kk = (tid >> 7) * 8;
    int rg = rowbase + rl;
    bool rvalid = rg < NA;
    const float* Hrow = Hin + (size_t)rg * KIN + kk;

    float bcol[8];
    *(float4*)&bcol[0] = *(const float4*)&bias[tx * 8];
    *(float4*)&bcol[4] = *(const float4*)&bias[tx * 8 + 4];

    {
        float4 a0 = make_float4(0,0,0,0), a1 = a0;
        if (rvalid) { a0 = *(const float4*)Hrow; a1 = *(const float4*)(Hrow + 4); }
        float4 w0 = ((const float4*)W)[tid];
        float4 w1 = ((const float4*)W)[tid + 256];
        sts_chunk(As[0], Ws[0], tid, a0, a1, w0, w1);
    }
    __syncthreads();

    u64 acc[8][4];
    #pragma unroll
    for (int i = 0; i < 8; i++)
        #pragma unroll
        for (int q = 0; q < 4; q++) acc[i][q] = 0ull;

    for (int c = 0; c < NCH; c++) {
        int buf = c & 1;
        float4 a0, a1, w0, w1;
        bool havenext = (c + 1 < NCH);
        if (havenext) {
            int k0 = (c + 1) * 16;
            a0 = make_float4(0,0,0,0); a1 = a0;
            if (rvalid) { a0 = *(const float4*)(Hrow + k0); a1 = *(const float4*)(Hrow + k0 + 4); }
            const float* wsrc = W + (size_t)k0 * 128;
            w0 = ((const float4*)wsrc)[tid];
            w1 = ((const float4*)wsrc)[tid + 256];
        }
        compute_chunk(As[buf], Ws[buf], tx, ty, acc);
        if (havenext) sts_chunk(As[buf ^ 1], Ws[buf ^ 1], tid, a0, a1, w0, w1);
        __syncthreads();
    }

    // prefetch mol ids for this thread's 8 rows
    int mm[8];
    #pragma unroll
    for (int i = 0; i < 8; i++) {
        int r = rowbase + ty * 8 + i;
        mm[i] = (r < NA) ? mol_ids[r] : -1;
    }

    int cur = -1;
    float run[8];
    #pragma unroll
    for (int i = 0; i < 8; i++) {
        float x[8];
        unpack2(acc[i][0], x[0], x[1]); unpack2(acc[i][1], x[2], x[3]);
        unpack2(acc[i][2], x[4], x[5]); unpack2(acc[i][3], x[6], x[7]);
        #pragma unroll
        for (int j = 0; j < 8; j++) x[j] += bcol[j];
        // softmax across the row (this thread's 8 cols + 16-lane shuffle group)
        float mx = x[0];
        #pragma unroll
        for (int j = 1; j < 8; j++) mx = fmaxf(mx, x[j]);
        #pragma unroll
        for (int o = 1; o < 16; o <<= 1) mx = fmaxf(mx, __shfl_xor_sync(0xffffffffu, mx, o));
        float s = 0.f;
        #pragma unroll
        for (int j = 0; j < 8; j++) { x[j] = __expf(x[j] - mx); s += x[j]; }
        #pragma unroll
        for (int o = 1; o < 16; o <<= 1) s += __shfl_xor_sync(0xffffffffu, s, o);
        float inv = 1.0f / s;
        #pragma unroll
        for (int j = 0; j < 8; j++) x[j] *= inv;

        if (mm[i] >= 0) {
            if (mm[i] != cur) {
                if (cur >= 0) {
                    #pragma unroll
                    for (int j = 0; j < 8; j++)
                        atomicAdd(&fp[(size_t)cur * 128 + tx * 8 + j], run[j]);
                }
                cur = mm[i];
                #pragma unroll
                for (int j = 0; j < 8; j++) run[j] = x[j];
            } else {
                #pragma unroll
                for (int j = 0; j < 8; j++) run[j] += x[j];
            }
        }
    }
    if (cur >= 0) {
        #pragma unroll
        for (int j = 0; j < 8; j++)
            atomicAdd(&fp[(size_t)cur * 128 + tx * 8 + j], run[j]);
    }
}

// ---------------- launch ----------------
extern "C" void kernel_launch(void* const* d_in, const int* in_sizes, int n_in,
                              void* d_out, int out_size) {
    const float *atom, *bond, *W0, *b0, *W1, *b1, *W2, *b2;
    const float *c1sW, *c1b, *c1d1, *c1d2, *c1d3, *c1d4;
    const float *c2sW, *c2b, *c2d1, *c2d2, *c2d3, *c2d4;
    const int *a1, *a2, *a3, *a4, *e1, *e2, *e3, *e4, *mol;

    if (in_sizes[0] == 12800000) {
        atom = (const float*)d_in[0];
        bond = (const float*)d_in[1];
        if (in_sizes[2] == 8192) {
            W0 = (const float*)d_in[2];  b0 = (const float*)d_in[3];
            W1 = (const float*)d_in[4];  b1 = (const float*)d_in[5];
            W2 = (const float*)d_in[6];  b2 = (const float*)d_in[7];
            c1sW = (const float*)d_in[8];  c1b = (const float*)d_in[9];
            c1d1 = (const float*)d_in[10]; c1d2 = (const float*)d_in[11];
            c1d3 = (const float*)d_in[12]; c1d4 = (const float*)d_in[13];
            c2sW = (const float*)d_in[14]; c2b = (const float*)d_in[15];
            c2d1 = (const float*)d_in[16]; c2d2 = (const float*)d_in[17];
            c2d3 = (const float*)d_in[18]; c2d4 = (const float*)d_in[19];
            a1 = (const int*)d_in[20]; a2 = (const int*)d_in[21];
            a3 = (const int*)d_in[22]; a4 = (const int*)d_in[23];
            e1 = (const int*)d_in[24]; e2 = (const int*)d_in[25];
            e3 = (const int*)d_in[26]; e4 = (const int*)d_in[27];
            mol = (const int*)d_in[28];
        } else if (in_sizes[3] == 50000) {
            a1 = (const int*)d_in[2];  e1 = (const int*)d_in[3];
            a2 = (const int*)d_in[4];  e2 = (const int*)d_in[5];
            a3 = (const int*)d_in[6];  e3 = (const int*)d_in[7];
            a4 = (const int*)d_in[8];  e4 = (const int*)d_in[9];
            mol = (const int*)d_in[10];
            W0 = (const float*)d_in[11]; b0 = (const float*)d_in[12];
            W1 = (const float*)d_in[13]; b1 = (const float*)d_in[14];
            W2 = (const float*)d_in[15]; b2 = (const float*)d_in[16];
            c1sW = (const float*)d_in[17]; c1b = (const float*)d_in[18];
            c1d1 = (const float*)d_in[19]; c1d2 = (const float*)d_in[20];
            c1d3 = (const float*)d_in[21]; c1d4 = (const float*)d_in[22];
            c2sW = (const float*)d_in[23]; c2b = (const float*)d_in[24];
            c2d1 = (const float*)d_in[25]; c2d2 = (const float*)d_in[26];
            c2d3 = (const float*)d_in[27]; c2d4 = (const float*)d_in[28];
        } else {
            a1 = (const int*)d_in[2];  a2 = (const int*)d_in[3];
            a3 = (const int*)d_in[4];  a4 = (const int*)d_in[5];
            e1 = (const int*)d_in[6];  e2 = (const int*)d_in[7];
            e3 = (const int*)d_in[8];  e4 = (const int*)d_in[9];
            mol = (const int*)d_in[10];
            W0 = (const float*)d_in[11]; b0 = (const float*)d_in[12];
            W1 = (const float*)d_in[13]; b1 = (const float*)d_in[14];
            W2 = (const float*)d_in[15]; b2 = (const float*)d_in[16];
            c1sW = (const float*)d_in[17]; c1b = (const float*)d_in[18];
            c1d1 = (const float*)d_in[19]; c1d2 = (const float*)d_in[20];
            c1d3 = (const float*)d_in[21]; c1d4 = (const float*)d_in[22];
            c2sW = (const float*)d_in[23]; c2b = (const float*)d_in[24];
            c2d1 = (const float*)d_in[25]; c2d2 = (const float*)d_in[26];
            c2d3 = (const float*)d_in[27]; c2d4 = (const float*)d_in[28];
        }
    } else {
        a1 = (const int*)d_in[0];  a2 = (const int*)d_in[1];
        a3 = (const int*)d_in[2];  a4 = (const int*)d_in[3];
        atom = (const float*)d_in[4];
        e1 = (const int*)d_in[5];  e2 = (const int*)d_in[6];
        e3 = (const int*)d_in[7];  e4 = (const int*)d_in[8];
        bond = (const float*)d_in[9];
        c1b = (const float*)d_in[10];
        c1d1 = (const float*)d_in[11]; c1d2 = (const float*)d_in[12];
        c1d3 = (const float*)d_in[13]; c1d4 = (const float*)d_in[14];
        c1sW = (const float*)d_in[15];
        c2b = (const float*)d_in[16];
        c2d1 = (const float*)d_in[17]; c2d2 = (const float*)d_in[18];
        c2d3 = (const float*)d_in[19]; c2d4 = (const float*)d_in[20];
        c2sW = (const float*)d_in[21];
        mol = (const int*)d_in[22];
        if (in_sizes[24] == 128) {
            W0 = (const float*)d_in[23]; b0 = (const float*)d_in[24];
            W1 = (const float*)d_in[25]; b1 = (const float*)d_in[26];
            W2 = (const float*)d_in[27]; b2 = (const float*)d_in[28];
        } else {
            W0 = (const float*)d_in[23]; W1 = (const float*)d_in[24];
            W2 = (const float*)d_in[25];
            b0 = (const float*)d_in[26]; b1 = (const float*)d_in[27];
            b2 = (const float*)d_in[28];
        }
    }

    float* fp = (float*)d_out;

    float *Hp, *Xp;
    cudaGetSymbolAddress((void**)&Hp, g_H);
    cudaGetSymbolAddress((void**)&Xp, g_X);

    cudaMemsetAsync(d_out, 0, (size_t)out_size * sizeof(float));
    zero_stats_kernel<<<1, 512>>>();

    // fp += segsum(softmax(atom @ W0 + b0))
    fp_kernel<64><<<FPB, 256>>>(atom, W0, b0, mol, fp);

    // layer 1 conv
    {
        long long total = (long long)NA * 36;
        int gblocks = (int)((total + 255) / 256);
        gather_kernel<64><<<gblocks, 256>>>(atom, bond, a1, a2, a3, a4, e1, e2, e3, e4);
    }
    conv_kernel<64><<<4 * TPD, 256>>>(c1sW, c1d1, c1d2, c1d3, c1d4, c1b, Hp, 0);
    norm_kernel<<<2048, 256>>>(Hp, 0);

    // fp += segsum(softmax(h1 @ W1 + b1))
    fp_kernel<128><<<FPB, 256>>>(Hp, W1, b1, mol, fp);

    // layer 2 conv
    {
        long long total = (long long)NA * 68;
        int gblocks = (int)((total + 255) / 256);
        gather_kernel<128><<<gblocks, 256>>>(Hp, bond, a1, a2, a3, a4, e1, e2, e3, e4);
    }
    conv_kernel<128><<<4 * TPD, 256>>>(c2sW, c2d1, c2d2, c2d3, c2d4, c2b, Xp, 256);
    norm_kernel<<<2048, 256>>>(Xp, 256);

    // fp += segsum(softmax(h2 @ W2 + b2))
    fp_kernel<128><<<FPB, 256>>>(Xp, W2, b2, mol, fp);
}